// round 12
// baseline (speedup 1.0000x reference)
#include <cuda_runtime.h>

typedef unsigned int u32;
typedef unsigned short u16;

#define CCH  192
#define HWSZ 16384
#define NTHR 384
#define EPSV 1e-6f

// ---- smem byte offsets ----
#define OFF_AH 0u          // A hi: 128px x 192ch bf16, 384B/row, XOR16 swizzle
#define OFF_AL 49152u      // A lo
#define OFF_TH 98304u      // T (q then t) hi   (gate partials overlay early)
#define OFF_TL 147456u     // T lo
#define OFF_W  196608u     // now only LN partials scratch
#define OFF_GS 221184u     // gates 3x128 f32
#define OFF_FB 222720u     // fb 196 f32
#define OFF_HB 223504u
#define OFF_PB 224272u
#define OFF_LW 225040u
#define OFF_LB 225808u
#define OFF_MU 226576u
#define OFF_RS 227088u
#define SMEM_TOTAL 227600
// py (fp32 y, [ch][128px] stride 512B, swizzled) overlays OFF_AH..98304

// B fragments in mma order: 18 regions = 3 gemms x 2 ci(96ch) x 3 wn(32ch).
// Region layout: [ks(12)][nt(4)][lane(32)] uint4 = {hi_b0, hi_b1, lo_b0, lo_b1}.
__device__ __align__(16) uint4 g_wf[27648];   // 18 * 1536

__device__ __forceinline__ u32 cvt2(float lo, float hi) {
    u32 r; asm("cvt.rn.bf16x2.f32 %0, %1, %2;" : "=r"(r) : "f"(hi), "f"(lo)); return r;
}
__device__ __forceinline__ void split2(float a, float b, u32& h2, u32& l2) {
    h2 = cvt2(a, b);
    float ah = __uint_as_float(h2 << 16);
    float bh = __uint_as_float(h2 & 0xFFFF0000u);
    l2 = cvt2(a - ah, b - bh);
}
__device__ __forceinline__ u32 smem_u32_of(const void* p) {
    u32 a;
    asm("{ .reg .u64 t; cvta.to.shared.u64 t, %1; cvt.u32.u64 %0, t; }" : "=r"(a) : "l"(p));
    return a;
}
__device__ __forceinline__ void ldsm4(u32& r0, u32& r1, u32& r2, u32& r3, u32 a) {
    asm volatile("ldmatrix.sync.aligned.m8n8.x4.shared.b16 {%0,%1,%2,%3}, [%4];"
                 : "=r"(r0), "=r"(r1), "=r"(r2), "=r"(r3) : "r"(a));
}
__device__ __forceinline__ void mma16816(float* d, u32 a0, u32 a1, u32 a2, u32 a3,
                                         u32 b0, u32 b1) {
    asm volatile(
        "mma.sync.aligned.m16n8k16.row.col.f32.bf16.bf16.f32 "
        "{%0,%1,%2,%3}, {%4,%5,%6,%7}, {%8,%9}, {%0,%1,%2,%3};"
        : "+f"(d[0]), "+f"(d[1]), "+f"(d[2]), "+f"(d[3])
        : "r"(a0), "r"(a1), "r"(a2), "r"(a3), "r"(b0), "r"(b1));
}

// ---- pre-kernel: build B fragments directly (one uint4 per thread) ----
// B[k][n] = W[ch = n][k].  b0 = rows 2*(l%4)+{0,1}, b1 = +8; col n = l>>2.
__global__ void CM_wconv_kernel(const float* __restrict__ fw,
                                const float* __restrict__ hwm,
                                const float* __restrict__ pw) {
    int idx = blockIdx.x * 256 + threadIdx.x;
    if (idx >= 27648) return;
    int lane = idx & 31;
    int nt   = (idx >> 5) & 3;
    int t7   = idx >> 7;          // r*12 + ks
    int ks   = t7 % 12;
    int r    = t7 / 12;           // 0..17
    int g    = r / 6;
    int ci   = (r % 6) / 3;
    int wn   = r % 3;
    const float* src = (g == 0) ? fw : (g == 1) ? hwm : pw;
    int ch = ci * 96 + wn * 32 + nt * 8 + (lane >> 2);
    int k0 = ks * 16 + (lane & 3) * 2;
    float v00 = src[ch * 192 + k0],     v01 = src[ch * 192 + k0 + 1];
    float v10 = src[ch * 192 + k0 + 8], v11 = src[ch * 192 + k0 + 9];
    u32 h0, l0, h1, l1;
    split2(v00, v01, h0, l0);
    split2(v10, v11, h1, l1);
    g_wf[idx] = make_uint4(h0, h1, l0, l1);
}

// one GEMM over full K=192 for one 96-ch chunk: 12 k-steps, B via prefetched LDG
__device__ __forceinline__ void gemm_ci(u32 smb, u32 offH, u32 offL, int region,
                                        float (&acc)[32], int wm, int lane) {
    const uint4* wf = g_wf + (size_t)region * 1536 + lane;
    const u32 aswz = (u32)(lane & 7) << 4;
    const u32 axor = ((u32)(lane >> 4) & 1u) * 16u;
    const u32 abase = ((u32)(32 * wm) + (u32)(lane & 7) + ((u32)(lane >> 3) & 1u) * 8u) * 384u;
    const u32 abh = smb + offH + abase;
    const u32 abl = smb + offL + abase;

    uint4 nb0 = wf[0], nb1 = wf[32], nb2 = wf[64], nb3 = wf[96];
    #pragma unroll 2
    for (int ks = 0; ks < 12; ++ks) {
        uint4 b0 = nb0, b1 = nb1, b2 = nb2, b3 = nb3;
        if (ks < 11) {
            const uint4* nf = wf + (size_t)(ks + 1) * 128;
            nb0 = nf[0]; nb1 = nf[32]; nb2 = nf[64]; nb3 = nf[96];
        }
        u32 acol = (32u * (u32)ks + axor) ^ aswz;
        u32 fa[16];
        ldsm4(fa[0],  fa[1],  fa[2],  fa[3],  abh + acol);
        ldsm4(fa[4],  fa[5],  fa[6],  fa[7],  abl + acol);
        ldsm4(fa[8],  fa[9],  fa[10], fa[11], abh + 6144u + acol);
        ldsm4(fa[12], fa[13], fa[14], fa[15], abl + 6144u + acol);
        #pragma unroll
        for (int mt = 0; mt < 2; ++mt) {
            float* a = &acc[mt * 16];
            u32 h0 = fa[8*mt+0], h1 = fa[8*mt+1], h2 = fa[8*mt+2], h3 = fa[8*mt+3];
            u32 l0 = fa[8*mt+4], l1 = fa[8*mt+5], l2 = fa[8*mt+6], l3 = fa[8*mt+7];
            mma16816(a + 0,  h0, h1, h2, h3, b0.x, b0.y);
            mma16816(a + 0,  h0, h1, h2, h3, b0.z, b0.w);
            mma16816(a + 0,  l0, l1, l2, l3, b0.x, b0.y);
            mma16816(a + 4,  h0, h1, h2, h3, b1.x, b1.y);
            mma16816(a + 4,  h0, h1, h2, h3, b1.z, b1.w);
            mma16816(a + 4,  l0, l1, l2, l3, b1.x, b1.y);
            mma16816(a + 8,  h0, h1, h2, h3, b2.x, b2.y);
            mma16816(a + 8,  h0, h1, h2, h3, b2.z, b2.w);
            mma16816(a + 8,  l0, l1, l2, l3, b2.x, b2.y);
            mma16816(a + 12, h0, h1, h2, h3, b3.x, b3.y);
            mma16816(a + 12, h0, h1, h2, h3, b3.z, b3.w);
            mma16816(a + 12, l0, l1, l2, l3, b3.x, b3.y);
        }
    }
}

__global__ void __launch_bounds__(NTHR)
CM_29540785062535_kernel(const float* __restrict__ x,
                         const float* __restrict__ xl,
                         const float* __restrict__ fw,
                         const float* __restrict__ fbg,
                         const float* __restrict__ hbg,
                         const float* __restrict__ pbg,
                         const float* __restrict__ lnwg,
                         const float* __restrict__ lnbg,
                         float* __restrict__ out,
                         int Nn)
{
    extern __shared__ char smem[];
    const u32 smb = smem_u32_of(smem);
    const int t    = threadIdx.x;
    const int lane = t & 31;
    const int w    = t >> 5;
    const int wm   = w & 3;        // 4 M positions (32px each)
    const int wn   = w >> 2;       // 3 N positions (32ch within 96-chunk)

    const int n   = blockIdx.x >> 7;
    const int hw0 = (blockIdx.x & 127) << 7;

    float* sfb = (float*)(smem + OFF_FB);
    float* shb = (float*)(smem + OFF_HB);
    float* spb = (float*)(smem + OFF_PB);
    float* slw = (float*)(smem + OFF_LW);
    float* slb = (float*)(smem + OFF_LB);
    float* gsf = (float*)(smem + OFF_GS);
    float* mus = (float*)(smem + OFF_MU);
    float* rss = (float*)(smem + OFF_RS);

    for (int i = t; i < 195; i += NTHR) sfb[i] = fbg[i];
    for (int i = t; i < 192; i += NTHR) {
        shb[i] = hbg[i]; spb[i] = pbg[i]; slw[i] = lnwg[i]; slb[i] = lnbg[i];
    }

    const int px4 = t & 31;
    const int cpb = t >> 5;

    // ---- phase 1: stage x -> AH/AL + gate partials (overlay TH) ----
    {
        const float* xb = x + ((size_t)n * CCH) * HWSZ + hw0;
        float* gpart = (float*)(smem + OFF_TH);
        float ga[12];
        #pragma unroll
        for (int m = 0; m < 12; ++m) ga[m] = 0.f;
        #pragma unroll 2
        for (int j = 0; j < 8; ++j) {
            int cp = cpb + 12 * j;
            int c = 2 * cp;
            float4 a = *(const float4*)(xb + (size_t)c * HWSZ + 4 * px4);
            float4 b = *(const float4*)(xb + (size_t)(c + 1) * HWSZ + 4 * px4);
            float av[4] = {a.x, a.y, a.z, a.w};
            float bv[4] = {b.x, b.y, b.z, b.w};
            #pragma unroll
            for (int jj = 0; jj < 4; ++jj) {
                u32 h2, l2;
                split2(av[jj], bv[jj], h2, l2);
                u32 px = (u32)(4 * px4 + jj);
                u32 off = px * 384u + (((u32)(2 * c)) ^ ((px & 7u) << 4));
                *(u32*)(smem + OFF_AH + off) = h2;
                *(u32*)(smem + OFF_AL + off) = l2;
            }
            #pragma unroll
            for (int l = 0; l < 3; ++l) {
                float w0 = __ldg(fw + (size_t)(192 + l) * 192 + c);
                float w1 = __ldg(fw + (size_t)(192 + l) * 192 + c + 1);
                #pragma unroll
                for (int jj = 0; jj < 4; ++jj)
                    ga[l * 4 + jj] = fmaf(w0, av[jj], fmaf(w1, bv[jj], ga[l * 4 + jj]));
            }
        }
        #pragma unroll
        for (int l = 0; l < 3; ++l)
            #pragma unroll
            for (int jj = 0; jj < 4; ++jj)
                gpart[cpb * 384 + l * 128 + 4 * px4 + jj] = ga[l * 4 + jj];
    }
    __syncthreads();
    {
        const float* gpart = (const float*)(smem + OFF_TH);
        float v = sfb[192 + (t >> 7)];
        #pragma unroll
        for (int g = 0; g < 12; ++g) v += gpart[g * 384 + t];
        gsf[t] = v;
    }
    __syncthreads();

    const int tq = lane & 3;
    const int gg = lane >> 2;

    // ---- GEMM1: q = x @ fw ; q+fb -> TH/TL ----
    #pragma unroll 1
    for (int ci = 0; ci < 2; ++ci) {
        float acc[32];
        #pragma unroll
        for (int m = 0; m < 32; ++m) acc[m] = 0.f;
        gemm_ci(smb, OFF_AH, OFF_AL, ci * 3 + wn, acc, wm, lane);
        #pragma unroll
        for (int mt = 0; mt < 2; ++mt)
            #pragma unroll
            for (int nt = 0; nt < 4; ++nt) {
                int ch0 = 96 * ci + 32 * wn + 8 * nt + 2 * tq;
                int r0 = 32 * wm + 16 * mt + gg;
                const float* a = &acc[mt * 16 + nt * 4];
                u32 o0 = (u32)r0 * 384u + (((u32)(2 * ch0)) ^ (((u32)r0 & 7u) << 4));
                u32 o1 = o0 + 8u * 384u;
                u32 h2, l2;
                split2(a[0] + sfb[ch0], a[1] + sfb[ch0 + 1], h2, l2);
                *(u32*)(smem + OFF_TH + o0) = h2;
                *(u32*)(smem + OFF_TL + o0) = l2;
                split2(a[2] + sfb[ch0], a[3] + sfb[ch0 + 1], h2, l2);
                *(u32*)(smem + OFF_TH + o1) = h2;
                *(u32*)(smem + OFF_TL + o1) = l2;
            }
    }
    __syncthreads();   // A fully read; T fully written

    // ---- ctx = sum_l gates[l]*x_list[l] -> AH/AL ----
    {
        const float* b0 = xl + ((size_t)(0 * Nn + n) * CCH) * HWSZ + hw0;
        const float* b1 = xl + ((size_t)(1 * Nn + n) * CCH) * HWSZ + hw0;
        const float* b2 = xl + ((size_t)(2 * Nn + n) * CCH) * HWSZ + hw0;
        float4 g0 = *(const float4*)(gsf + 0 * 128 + 4 * px4);
        float4 g1 = *(const float4*)(gsf + 1 * 128 + 4 * px4);
        float4 g2 = *(const float4*)(gsf + 2 * 128 + 4 * px4);
        float g0v[4] = {g0.x, g0.y, g0.z, g0.w};
        float g1v[4] = {g1.x, g1.y, g1.z, g1.w};
        float g2v[4] = {g2.x, g2.y, g2.z, g2.w};
        #pragma unroll 2
        for (int j = 0; j < 8; ++j) {
            int cp = cpb + 12 * j;
            int c = 2 * cp;
            size_t oa = (size_t)c * HWSZ + 4 * px4;
            size_t ob = oa + HWSZ;
            float4 a0 = *(const float4*)(b0 + oa), a1 = *(const float4*)(b1 + oa), a2 = *(const float4*)(b2 + oa);
            float4 c0 = *(const float4*)(b0 + ob), c1 = *(const float4*)(b1 + ob), c2 = *(const float4*)(b2 + ob);
            float a0v[4] = {a0.x, a0.y, a0.z, a0.w};
            float a1v[4] = {a1.x, a1.y, a1.z, a1.w};
            float a2v[4] = {a2.x, a2.y, a2.z, a2.w};
            float c0v[4] = {c0.x, c0.y, c0.z, c0.w};
            float c1v[4] = {c1.x, c1.y, c1.z, c1.w};
            float c2v[4] = {c2.x, c2.y, c2.z, c2.w};
            #pragma unroll
            for (int jj = 0; jj < 4; ++jj) {
                float va = fmaf(g2v[jj], a2v[jj], fmaf(g1v[jj], a1v[jj], g0v[jj] * a0v[jj]));
                float vb = fmaf(g2v[jj], c2v[jj], fmaf(g1v[jj], c1v[jj], g0v[jj] * c0v[jj]));
                u32 h2, l2;
                split2(va, vb, h2, l2);
                u32 px = (u32)(4 * px4 + jj);
                u32 off = px * 384u + (((u32)(2 * c)) ^ ((px & 7u) << 4));
                *(u32*)(smem + OFF_AH + off) = h2;
                *(u32*)(smem + OFF_AL + off) = l2;
            }
        }
    }
    __syncthreads();   // ctx visible before GEMM2 reads A

    // ---- GEMM2: mod = ctx @ hw ; t = q*(mod+hb) -> TH/TL in place ----
    #pragma unroll 1
    for (int ci = 0; ci < 2; ++ci) {
        float acc[32];
        #pragma unroll
        for (int m = 0; m < 32; ++m) acc[m] = 0.f;
        gemm_ci(smb, OFF_AH, OFF_AL, 6 + ci * 3 + wn, acc, wm, lane);
        #pragma unroll
        for (int mt = 0; mt < 2; ++mt)
            #pragma unroll
            for (int nt = 0; nt < 4; ++nt) {
                int ch0 = 96 * ci + 32 * wn + 8 * nt + 2 * tq;
                int r0 = 32 * wm + 16 * mt + gg;
                const float* a = &acc[mt * 16 + nt * 4];
                u32 o0 = (u32)r0 * 384u + (((u32)(2 * ch0)) ^ (((u32)r0 & 7u) << 4));
                u32 o1 = o0 + 8u * 384u;
                u32 qh = *(u32*)(smem + OFF_TH + o0);
                u32 ql = *(u32*)(smem + OFF_TL + o0);
                float q0 = __uint_as_float(qh << 16) + __uint_as_float(ql << 16);
                float q1 = __uint_as_float(qh & 0xFFFF0000u) + __uint_as_float(ql & 0xFFFF0000u);
                float t0 = q0 * (a[0] + shb[ch0]);
                float t1 = q1 * (a[1] + shb[ch0 + 1]);
                u32 h2, l2;
                split2(t0, t1, h2, l2);
                *(u32*)(smem + OFF_TH + o0) = h2;
                *(u32*)(smem + OFF_TL + o0) = l2;
                qh = *(u32*)(smem + OFF_TH + o1);
                ql = *(u32*)(smem + OFF_TL + o1);
                q0 = __uint_as_float(qh << 16) + __uint_as_float(ql << 16);
                q1 = __uint_as_float(qh & 0xFFFF0000u) + __uint_as_float(ql & 0xFFFF0000u);
                t0 = q0 * (a[2] + shb[ch0]);
                t1 = q1 * (a[3] + shb[ch0 + 1]);
                split2(t0, t1, h2, l2);
                *(u32*)(smem + OFF_TH + o1) = h2;
                *(u32*)(smem + OFF_TL + o1) = l2;
            }
    }
    __syncthreads();   // t fully written before GEMM3 reads it as A

    // ---- GEMM3: y = t @ pw ; y+pb -> py fp32 [ch][128px] (overlays A) ----
    #pragma unroll 1
    for (int ci = 0; ci < 2; ++ci) {
        float acc[32];
        #pragma unroll
        for (int m = 0; m < 32; ++m) acc[m] = 0.f;
        gemm_ci(smb, OFF_TH, OFF_TL, 12 + ci * 3 + wn, acc, wm, lane);
        #pragma unroll
        for (int mt = 0; mt < 2; ++mt)
            #pragma unroll
            for (int nt = 0; nt < 4; ++nt) {
                int ch0 = 96 * ci + 32 * wn + 8 * nt + 2 * tq;
                int r0 = 32 * wm + 16 * mt + gg;
                int r1 = r0 + 8;
                const float* a = &acc[mt * 16 + nt * 4];
                u32 s0 = (u32)ch0 * 512u + (((u32)(4 * r0)) ^ (((u32)ch0 & 7u) << 4));
                u32 s1 = (u32)(ch0 + 1) * 512u + (((u32)(4 * r0)) ^ (((u32)(ch0 + 1) & 7u) << 4));
                u32 s2 = (u32)ch0 * 512u + (((u32)(4 * r1)) ^ (((u32)ch0 & 7u) << 4));
                u32 s3 = (u32)(ch0 + 1) * 512u + (((u32)(4 * r1)) ^ (((u32)(ch0 + 1) & 7u) << 4));
                *(float*)(smem + s0) = a[0] + spb[ch0];
                *(float*)(smem + s1) = a[1] + spb[ch0 + 1];
                *(float*)(smem + s2) = a[2] + spb[ch0];
                *(float*)(smem + s3) = a[3] + spb[ch0 + 1];
            }
    }
    __syncthreads();

    // ---- LN stats: 3 segs x 128 px (partials in OFF_W scratch) ----
    {
        float* ps = (float*)(smem + OFF_W);
        float* qs = ps + 384;
        int seg = t >> 7, px = t & 127;
        float s = 0.f, s2 = 0.f;
        #pragma unroll 4
        for (int ch = 64 * seg; ch < 64 * seg + 64; ++ch) {
            float v = *(float*)(smem + (u32)ch * 512u + (((u32)(4 * px)) ^ (((u32)ch & 7u) << 4)));
            s += v;
            s2 = fmaf(v, v, s2);
        }
        ps[t] = s; qs[t] = s2;
    }
    __syncthreads();
    if (t < 128) {
        float* ps = (float*)(smem + OFF_W);
        float* qs = ps + 384;
        float st = ps[t] + ps[t + 128] + ps[t + 256];
        float qt = qs[t] + qs[t + 128] + qs[t + 256];
        float mu  = st * (1.0f / CCH);
        float var = qt * (1.0f / CCH) - mu * mu;
        mus[t] = mu;
        rss[t] = rsqrtf(var + EPSV);
    }
    __syncthreads();

    // ---- normalize + residual + coalesced store ----
    {
        const float* xb = x + ((size_t)n * CCH) * HWSZ + hw0;
        float* ob = out + ((size_t)n * CCH) * HWSZ + hw0;
        #pragma unroll 4
        for (int u = 0; u < 16; ++u) {
            int f4 = t + 384 * u;
            int c = f4 >> 5, L = f4 & 31;
            float4 y = *(const float4*)(smem + (u32)c * 512u + (((u32)(16 * L)) ^ (((u32)c & 7u) << 4)));
            float4 xv = *(const float4*)(xb + (size_t)c * HWSZ + 4 * L);
            float4 m = *(const float4*)(mus + 4 * L);
            float4 r = *(const float4*)(rss + 4 * L);
            float lw = slw[c], lb = slb[c];
            float4 o;
            o.x = fmaf(lw * (y.x - m.x), r.x, lb) + xv.x;
            o.y = fmaf(lw * (y.y - m.y), r.y, lb) + xv.y;
            o.z = fmaf(lw * (y.z - m.z), r.z, lb) + xv.z;
            o.w = fmaf(lw * (y.w - m.w), r.w, lb) + xv.w;
            *(float4*)(ob + (size_t)c * HWSZ + 4 * L) = o;
        }
    }
}

extern "C" void kernel_launch(void* const* d_in, const int* in_sizes, int n_in,
                              void* d_out, int out_size) {
    const float* x   = (const float*)d_in[0];
    const float* xl  = (const float*)d_in[1];
    const float* fw  = (const float*)d_in[2];
    const float* fb  = (const float*)d_in[3];
    const float* hwm = (const float*)d_in[4];
    const float* hb  = (const float*)d_in[5];
    const float* pw  = (const float*)d_in[6];
    const float* pb  = (const float*)d_in[7];
    const float* lnw = (const float*)d_in[8];
    const float* lnb = (const float*)d_in[9];
    float* out = (float*)d_out;

    int Nn = in_sizes[0] / (CCH * HWSZ);

    CM_wconv_kernel<<<(27648 + 255) / 256, 256>>>(fw, hwm, pw);

    cudaFuncSetAttribute(CM_29540785062535_kernel,
                         cudaFuncAttributeMaxDynamicSharedMemorySize, SMEM_TOTAL);

    int blocks = Nn * (HWSZ / 128);   // 2048
    CM_29540785062535_kernel<<<blocks, NTHR, SMEM_TOTAL>>>(
        x, xl, fw, fb, hb, pb, lnw, lnb, out, Nn);
}

// round 13
// speedup vs baseline: 1.0708x; 1.0708x over previous
#include <cuda_runtime.h>

typedef unsigned int u32;
typedef unsigned short u16;

#define CCH  192
#define HWSZ 16384
#define NTHR 512
#define EPSV 1e-6f

// ---- smem byte offsets ----
#define OFF_AH 0u          // A hi: 128px x 192ch bf16, 384B/row, XOR16 swizzle
#define OFF_AL 49152u      // A lo
#define OFF_TH 98304u      // T (q then t) hi   (gate partials overlay early)
#define OFF_TL 147456u     // T lo
#define OFF_W  196608u     // B k-sixth stage: 192ch x (32k hi | 32k lo) 128B/row = 24576B
#define OFF_GS 221184u     // gates 3x128 f32
#define OFF_FB 222720u     // fb 196 f32
#define OFF_HB 223504u
#define OFF_PB 224272u
#define OFF_LW 225040u
#define OFF_LB 225808u
#define OFF_MU 226576u
#define OFF_RS 227088u
#define SMEM_TOTAL 227600
// py (fp32 y, [ch][128px] stride 512B, swizzled) overlays OFF_AH..98304
// LN partials overlay OFF_W

// 18 regions = 3 gemms x 6 k-sixths; each 192 rows x 128B. 442368 B.
__device__ __align__(16) u16 g_wc[221184];

__device__ __forceinline__ u32 cvt2(float lo, float hi) {
    u32 r; asm("cvt.rn.bf16x2.f32 %0, %1, %2;" : "=r"(r) : "f"(hi), "f"(lo)); return r;
}
__device__ __forceinline__ void split2(float a, float b, u32& h2, u32& l2) {
    h2 = cvt2(a, b);
    float ah = __uint_as_float(h2 << 16);
    float bh = __uint_as_float(h2 & 0xFFFF0000u);
    l2 = cvt2(a - ah, b - bh);
}
__device__ __forceinline__ u32 smem_u32_of(const void* p) {
    u32 a;
    asm("{ .reg .u64 t; cvta.to.shared.u64 t, %1; cvt.u32.u64 %0, t; }" : "=r"(a) : "l"(p));
    return a;
}
__device__ __forceinline__ void ldsm4(u32& r0, u32& r1, u32& r2, u32& r3, u32 a) {
    asm volatile("ldmatrix.sync.aligned.m8n8.x4.shared.b16 {%0,%1,%2,%3}, [%4];"
                 : "=r"(r0), "=r"(r1), "=r"(r2), "=r"(r3) : "r"(a));
}
__device__ __forceinline__ void mma16816(float* d, u32 a0, u32 a1, u32 a2, u32 a3,
                                         u32 b0, u32 b1) {
    asm volatile(
        "mma.sync.aligned.m16n8k16.row.col.f32.bf16.bf16.f32 "
        "{%0,%1,%2,%3}, {%4,%5,%6,%7}, {%8,%9}, {%0,%1,%2,%3};"
        : "+f"(d[0]), "+f"(d[1]), "+f"(d[2]), "+f"(d[3])
        : "r"(a0), "r"(a1), "r"(a2), "r"(a3), "r"(b0), "r"(b1));
}

// ---- pre-kernel: fp32 weights -> bf16 hi/lo, 18 k-sixth regions ----
// Region row = out-channel (192 rows x 128B). 128B row = 8 slots of 16B:
// slot_h = kk>>3 (0..3), slot_l = 4 + (kk>>3); stored at (slot ^ (ch&7))<<4.
__global__ void CM_wconv_kernel(const float* __restrict__ fw,
                                const float* __restrict__ hwm,
                                const float* __restrict__ pw) {
    int idx = blockIdx.x * 256 + threadIdx.x;
    if (idx >= 3 * 192 * 192) return;
    int g = idx / (192 * 192);
    int rem = idx - g * (192 * 192);
    int ch = rem / 192, k = rem - (rem / 192) * 192;
    const float* src = (g == 0) ? fw : (g == 1) ? hwm : pw;
    float w = src[ch * 192 + k];
    u32 h2 = cvt2(w, 0.f);
    float hf = __uint_as_float(h2 << 16);
    u32 l2 = cvt2(w - hf, 0.f);
    int region = g * 6 + (k >> 5);
    int kk = k & 31;
    u32 base = (u32)region * 24576u + (u32)ch * 128u + (u32)(kk & 7) * 2u;
    u32 sw = (u32)(ch & 7);
    u32 sh = (u32)(kk >> 3);
    u32 sl = sh + 4u;
    g_wc[(base + ((sh ^ sw) << 4)) >> 1] = (u16)(h2 & 0xFFFFu);
    g_wc[(base + ((sl ^ sw) << 4)) >> 1] = (u16)(l2 & 0xFFFFu);
}

// full GEMM over K=192: 6 stages x 2 k-steps; Mt=4 x Nt=3 warp tile
__device__ __forceinline__ void gemm_full(char* smem, u32 smb, u32 offH, u32 offL,
                                          int gidx, float (&acc)[48],
                                          int wm, int wn, int lane, int t) {
    const uint4* gw = (const uint4*)g_wc;   // 1536 uint4 per region
    const u32 aswz = (u32)(lane & 7) << 4;
    const u32 axor = ((u32)(lane >> 4) & 1u) * 16u;
    const u32 abase = ((u32)(64 * wm) + (u32)(lane & 7) + ((u32)(lane >> 3) & 1u) * 8u) * 384u;
    const u32 abh = smb + offH + abase;
    const u32 abl = smb + offL + abase;
    // B: row = 24*wn + 8*nt + (lane&7); slot = hi/lo*4 + 2*ks2 + khalf, XOR (lane&7)
    const u32 bb = smb + OFF_W + ((u32)(24 * wn) + (u32)(lane & 7)) * 128u;
    const u32 slotbase = ((u32)(lane >> 4) & 1u) * 4u + ((u32)(lane >> 3) & 1u);

    uint4 ph[3];
    #pragma unroll
    for (int j = 0; j < 3; ++j) ph[j] = gw[(size_t)gidx * 9216 + t + 512 * j];

    #pragma unroll 1
    for (int st = 0; st < 6; ++st) {
        #pragma unroll
        for (int j = 0; j < 3; ++j) ((uint4*)(smem + OFF_W))[t + 512 * j] = ph[j];
        __syncthreads();
        if (st < 5) {
            #pragma unroll
            for (int j = 0; j < 3; ++j)
                ph[j] = gw[(size_t)gidx * 9216 + (size_t)(st + 1) * 1536 + t + 512 * j];
        }
        #pragma unroll
        for (int ks2 = 0; ks2 < 2; ++ks2) {
            int ks = 2 * st + ks2;
            u32 acol = (32u * (u32)ks + axor) ^ aswz;
            u32 fa[32];
            #pragma unroll
            for (int mt = 0; mt < 4; ++mt) {
                u32 off = (u32)(16 * mt) * 384u + acol;
                ldsm4(fa[8*mt+0], fa[8*mt+1], fa[8*mt+2], fa[8*mt+3], abh + off);
                ldsm4(fa[8*mt+4], fa[8*mt+5], fa[8*mt+6], fa[8*mt+7], abl + off);
            }
            u32 boff = ((slotbase + 2u * (u32)ks2) ^ (u32)(lane & 7)) << 4;
            u32 fb[12];
            ldsm4(fb[0], fb[1], fb[2],  fb[3],  bb + boff);
            ldsm4(fb[4], fb[5], fb[6],  fb[7],  bb + 1024u + boff);
            ldsm4(fb[8], fb[9], fb[10], fb[11], bb + 2048u + boff);
            #pragma unroll
            for (int mt = 0; mt < 4; ++mt)
                #pragma unroll
                for (int nt = 0; nt < 3; ++nt) {
                    float* a = &acc[(mt * 3 + nt) * 4];
                    mma16816(a, fa[8*mt+0], fa[8*mt+1], fa[8*mt+2], fa[8*mt+3],
                             fb[4*nt+0], fb[4*nt+1]);                     // hh
                    mma16816(a, fa[8*mt+0], fa[8*mt+1], fa[8*mt+2], fa[8*mt+3],
                             fb[4*nt+2], fb[4*nt+3]);                     // h*lo(B)
                    mma16816(a, fa[8*mt+4], fa[8*mt+5], fa[8*mt+6], fa[8*mt+7],
                             fb[4*nt+0], fb[4*nt+1]);                     // lo(A)*h
                }
        }
        __syncthreads();
    }
}

__global__ void __launch_bounds__(NTHR)
CM_29540785062535_kernel(const float* __restrict__ x,
                         const float* __restrict__ xl,
                         const float* __restrict__ fw,
                         const float* __restrict__ fbg,
                         const float* __restrict__ hbg,
                         const float* __restrict__ pbg,
                         const float* __restrict__ lnwg,
                         const float* __restrict__ lnbg,
                         float* __restrict__ out,
                         int Nn)
{
    extern __shared__ char smem[];
    const u32 smb = smem_u32_of(smem);
    const int t    = threadIdx.x;
    const int lane = t & 31;
    const int w    = t >> 5;
    const int wm   = w & 1;        // 2 M positions (64px each)
    const int wn   = w >> 1;       // 8 N positions (24ch each)

    const int n   = blockIdx.x >> 7;
    const int hw0 = (blockIdx.x & 127) << 7;

    float* sfb = (float*)(smem + OFF_FB);
    float* shb = (float*)(smem + OFF_HB);
    float* spb = (float*)(smem + OFF_PB);
    float* slw = (float*)(smem + OFF_LW);
    float* slb = (float*)(smem + OFF_LB);
    float* gsf = (float*)(smem + OFF_GS);
    float* mus = (float*)(smem + OFF_MU);
    float* rss = (float*)(smem + OFF_RS);

    for (int i = t; i < 195; i += NTHR) sfb[i] = fbg[i];
    for (int i = t; i < 192; i += NTHR) {
        shb[i] = hbg[i]; spb[i] = pbg[i]; slw[i] = lnwg[i]; slb[i] = lnbg[i];
    }

    const int px4 = t & 31;
    const int cpb = t >> 5;        // 0..15

    // ---- phase 1: stage x -> AH/AL + gate partials (overlay TH) ----
    {
        const float* xb = x + ((size_t)n * CCH) * HWSZ + hw0;
        float* gpart = (float*)(smem + OFF_TH);
        float ga[12];
        #pragma unroll
        for (int m = 0; m < 12; ++m) ga[m] = 0.f;
        #pragma unroll 2
        for (int j = 0; j < 6; ++j) {
            int cp = cpb + 16 * j;           // 0..95
            int c = 2 * cp;
            float4 a = *(const float4*)(xb + (size_t)c * HWSZ + 4 * px4);
            float4 b = *(const float4*)(xb + (size_t)(c + 1) * HWSZ + 4 * px4);
            float av[4] = {a.x, a.y, a.z, a.w};
            float bv[4] = {b.x, b.y, b.z, b.w};
            #pragma unroll
            for (int jj = 0; jj < 4; ++jj) {
                u32 h2, l2;
                split2(av[jj], bv[jj], h2, l2);
                u32 px = (u32)(4 * px4 + jj);
                u32 off = px * 384u + (((u32)(2 * c)) ^ ((px & 7u) << 4));
                *(u32*)(smem + OFF_AH + off) = h2;
                *(u32*)(smem + OFF_AL + off) = l2;
            }
            #pragma unroll
            for (int l = 0; l < 3; ++l) {
                float w0 = __ldg(fw + (size_t)(192 + l) * 192 + c);
                float w1 = __ldg(fw + (size_t)(192 + l) * 192 + c + 1);
                #pragma unroll
                for (int jj = 0; jj < 4; ++jj)
                    ga[l * 4 + jj] = fmaf(w0, av[jj], fmaf(w1, bv[jj], ga[l * 4 + jj]));
            }
        }
        #pragma unroll
        for (int l = 0; l < 3; ++l)
            #pragma unroll
            for (int jj = 0; jj < 4; ++jj)
                gpart[cpb * 384 + l * 128 + 4 * px4 + jj] = ga[l * 4 + jj];
    }
    __syncthreads();
    if (t < 384) {
        const float* gpart = (const float*)(smem + OFF_TH);
        float v = sfb[192 + (t >> 7)];
        #pragma unroll
        for (int g = 0; g < 16; ++g) v += gpart[g * 384 + t];
        gsf[t] = v;
    }
    __syncthreads();

    const int tq = lane & 3;
    const int gg = lane >> 2;

    float acc[48];

    // ---- GEMM1: q = x @ fw ; q+fb -> TH/TL ----
    #pragma unroll
    for (int m = 0; m < 48; ++m) acc[m] = 0.f;
    gemm_full(smem, smb, OFF_AH, OFF_AL, 0, acc, wm, wn, lane, t);
    #pragma unroll
    for (int mt = 0; mt < 4; ++mt)
        #pragma unroll
        for (int nt = 0; nt < 3; ++nt) {
            int ch0 = 24 * wn + 8 * nt + 2 * tq;
            int r0 = 64 * wm + 16 * mt + gg;
            const float* a = &acc[(mt * 3 + nt) * 4];
            u32 o0 = (u32)r0 * 384u + (((u32)(2 * ch0)) ^ (((u32)r0 & 7u) << 4));
            u32 o1 = o0 + 8u * 384u;
            u32 h2, l2;
            split2(a[0] + sfb[ch0], a[1] + sfb[ch0 + 1], h2, l2);
            *(u32*)(smem + OFF_TH + o0) = h2;
            *(u32*)(smem + OFF_TL + o0) = l2;
            split2(a[2] + sfb[ch0], a[3] + sfb[ch0 + 1], h2, l2);
            *(u32*)(smem + OFF_TH + o1) = h2;
            *(u32*)(smem + OFF_TL + o1) = l2;
        }

    // ---- ctx = sum_l gates[l]*x_list[l] -> AH/AL ----
    // (A fully read before gemm_full's final sync; GEMM2's first stage sync
    //  publishes these writes before any warp ldsm's them)
    {
        const float* b0 = xl + ((size_t)(0 * Nn + n) * CCH) * HWSZ + hw0;
        const float* b1 = xl + ((size_t)(1 * Nn + n) * CCH) * HWSZ + hw0;
        const float* b2 = xl + ((size_t)(2 * Nn + n) * CCH) * HWSZ + hw0;
        float4 g0 = *(const float4*)(gsf + 0 * 128 + 4 * px4);
        float4 g1 = *(const float4*)(gsf + 1 * 128 + 4 * px4);
        float4 g2 = *(const float4*)(gsf + 2 * 128 + 4 * px4);
        float g0v[4] = {g0.x, g0.y, g0.z, g0.w};
        float g1v[4] = {g1.x, g1.y, g1.z, g1.w};
        float g2v[4] = {g2.x, g2.y, g2.z, g2.w};
        #pragma unroll 2
        for (int j = 0; j < 6; ++j) {
            int cp = cpb + 16 * j;
            int c = 2 * cp;
            size_t oa = (size_t)c * HWSZ + 4 * px4;
            size_t ob = oa + HWSZ;
            float4 a0 = *(const float4*)(b0 + oa), a1 = *(const float4*)(b1 + oa), a2 = *(const float4*)(b2 + oa);
            float4 c0 = *(const float4*)(b0 + ob), c1 = *(const float4*)(b1 + ob), c2 = *(const float4*)(b2 + ob);
            float a0v[4] = {a0.x, a0.y, a0.z, a0.w};
            float a1v[4] = {a1.x, a1.y, a1.z, a1.w};
            float a2v[4] = {a2.x, a2.y, a2.z, a2.w};
            float c0v[4] = {c0.x, c0.y, c0.z, c0.w};
            float c1v[4] = {c1.x, c1.y, c1.z, c1.w};
            float c2v[4] = {c2.x, c2.y, c2.z, c2.w};
            #pragma unroll
            for (int jj = 0; jj < 4; ++jj) {
                float va = fmaf(g2v[jj], a2v[jj], fmaf(g1v[jj], a1v[jj], g0v[jj] * a0v[jj]));
                float vb = fmaf(g2v[jj], c2v[jj], fmaf(g1v[jj], c1v[jj], g0v[jj] * c0v[jj]));
                u32 h2, l2;
                split2(va, vb, h2, l2);
                u32 px = (u32)(4 * px4 + jj);
                u32 off = px * 384u + (((u32)(2 * c)) ^ ((px & 7u) << 4));
                *(u32*)(smem + OFF_AH + off) = h2;
                *(u32*)(smem + OFF_AL + off) = l2;
            }
        }
    }
    __syncthreads();

    // ---- GEMM2: mod = ctx @ hw ; t = q*(mod+hb) -> TH/TL in place ----
    #pragma unroll
    for (int m = 0; m < 48; ++m) acc[m] = 0.f;
    gemm_full(smem, smb, OFF_AH, OFF_AL, 1, acc, wm, wn, lane, t);
    #pragma unroll
    for (int mt = 0; mt < 4; ++mt)
        #pragma unroll
        for (int nt = 0; nt < 3; ++nt) {
            int ch0 = 24 * wn + 8 * nt + 2 * tq;
            int r0 = 64 * wm + 16 * mt + gg;
            const float* a = &acc[(mt * 3 + nt) * 4];
            u32 o0 = (u32)r0 * 384u + (((u32)(2 * ch0)) ^ (((u32)r0 & 7u) << 4));
            u32 o1 = o0 + 8u * 384u;
            u32 qh = *(u32*)(smem + OFF_TH + o0);
            u32 ql = *(u32*)(smem + OFF_TL + o0);
            float q0 = __uint_as_float(qh << 16) + __uint_as_float(ql << 16);
            float q1 = __uint_as_float(qh & 0xFFFF0000u) + __uint_as_float(ql & 0xFFFF0000u);
            float t0 = q0 * (a[0] + shb[ch0]);
            float t1 = q1 * (a[1] + shb[ch0 + 1]);
            u32 h2, l2;
            split2(t0, t1, h2, l2);
            *(u32*)(smem + OFF_TH + o0) = h2;
            *(u32*)(smem + OFF_TL + o0) = l2;
            qh = *(u32*)(smem + OFF_TH + o1);
            ql = *(u32*)(smem + OFF_TL + o1);
            q0 = __uint_as_float(qh << 16) + __uint_as_float(ql << 16);
            q1 = __uint_as_float(qh & 0xFFFF0000u) + __uint_as_float(ql & 0xFFFF0000u);
            t0 = q0 * (a[2] + shb[ch0]);
            t1 = q1 * (a[3] + shb[ch0 + 1]);
            split2(t0, t1, h2, l2);
            *(u32*)(smem + OFF_TH + o1) = h2;
            *(u32*)(smem + OFF_TL + o1) = l2;
        }
    __syncthreads();   // t fully written before GEMM3 reads it as A

    // ---- GEMM3: y = t @ pw ; y+pb -> py fp32 [ch][128px] (overlays A) ----
    #pragma unroll
    for (int m = 0; m < 48; ++m) acc[m] = 0.f;
    gemm_full(smem, smb, OFF_TH, OFF_TL, 2, acc, wm, wn, lane, t);
    #pragma unroll
    for (int mt = 0; mt < 4; ++mt)
        #pragma unroll
        for (int nt = 0; nt < 3; ++nt) {
            int ch0 = 24 * wn + 8 * nt + 2 * tq;
            int r0 = 64 * wm + 16 * mt + gg;
            int r1 = r0 + 8;
            const float* a = &acc[(mt * 3 + nt) * 4];
            u32 s0 = (u32)ch0 * 512u + (((u32)(4 * r0)) ^ (((u32)ch0 & 7u) << 4));
            u32 s1 = (u32)(ch0 + 1) * 512u + (((u32)(4 * r0)) ^ (((u32)(ch0 + 1) & 7u) << 4));
            u32 s2 = (u32)ch0 * 512u + (((u32)(4 * r1)) ^ (((u32)ch0 & 7u) << 4));
            u32 s3 = (u32)(ch0 + 1) * 512u + (((u32)(4 * r1)) ^ (((u32)(ch0 + 1) & 7u) << 4));
            *(float*)(smem + s0) = a[0] + spb[ch0];
            *(float*)(smem + s1) = a[1] + spb[ch0 + 1];
            *(float*)(smem + s2) = a[2] + spb[ch0];
            *(float*)(smem + s3) = a[3] + spb[ch0 + 1];
        }
    __syncthreads();

    // ---- LN stats: 4 segs x 128 px (partials in OFF_W scratch) ----
    {
        float* ps = (float*)(smem + OFF_W);
        float* qs = ps + 512;
        int seg = t >> 7, px = t & 127;
        float s = 0.f, s2 = 0.f;
        #pragma unroll 4
        for (int ch = 48 * seg; ch < 48 * seg + 48; ++ch) {
            float v = *(float*)(smem + (u32)ch * 512u + (((u32)(4 * px)) ^ (((u32)ch & 7u) << 4)));
            s += v;
            s2 = fmaf(v, v, s2);
        }
        ps[t] = s; qs[t] = s2;
    }
    __syncthreads();
    if (t < 128) {
        float* ps = (float*)(smem + OFF_W);
        float* qs = ps + 512;
        float st = (ps[t] + ps[t + 128]) + (ps[t + 256] + ps[t + 384]);
        float qt = (qs[t] + qs[t + 128]) + (qs[t + 256] + qs[t + 384]);
        float mu  = st * (1.0f / CCH);
        float var = qt * (1.0f / CCH) - mu * mu;
        mus[t] = mu;
        rss[t] = rsqrtf(var + EPSV);
    }
    __syncthreads();

    // ---- normalize + residual + coalesced store ----
    {
        const float* xb = x + ((size_t)n * CCH) * HWSZ + hw0;
        float* ob = out + ((size_t)n * CCH) * HWSZ + hw0;
        #pragma unroll 4
        for (int u = 0; u < 12; ++u) {
            int f4 = t + 512 * u;
            int c = f4 >> 5, L = f4 & 31;
            float4 y = *(const float4*)(smem + (u32)c * 512u + (((u32)(16 * L)) ^ (((u32)c & 7u) << 4)));
            float4 xv = *(const float4*)(xb + (size_t)c * HWSZ + 4 * L);
            float4 m = *(const float4*)(mus + 4 * L);
            float4 r = *(const float4*)(rss + 4 * L);
            float lw = slw[c], lb = slb[c];
            float4 o;
            o.x = fmaf(lw * (y.x - m.x), r.x, lb) + xv.x;
            o.y = fmaf(lw * (y.y - m.y), r.y, lb) + xv.y;
            o.z = fmaf(lw * (y.z - m.z), r.z, lb) + xv.z;
            o.w = fmaf(lw * (y.w - m.w), r.w, lb) + xv.w;
            *(float4*)(ob + (size_t)c * HWSZ + 4 * L) = o;
        }
    }
}

extern "C" void kernel_launch(void* const* d_in, const int* in_sizes, int n_in,
                              void* d_out, int out_size) {
    const float* x   = (const float*)d_in[0];
    const float* xl  = (const float*)d_in[1];
    const float* fw  = (const float*)d_in[2];
    const float* fb  = (const float*)d_in[3];
    const float* hwm = (const float*)d_in[4];
    const float* hb  = (const float*)d_in[5];
    const float* pw  = (const float*)d_in[6];
    const float* pb  = (const float*)d_in[7];
    const float* lnw = (const float*)d_in[8];
    const float* lnb = (const float*)d_in[9];
    float* out = (float*)d_out;

    int Nn = in_sizes[0] / (CCH * HWSZ);

    CM_wconv_kernel<<<(3 * 192 * 192 + 255) / 256, 256>>>(fw, hwm, pw);

    cudaFuncSetAttribute(CM_29540785062535_kernel,
                         cudaFuncAttributeMaxDynamicSharedMemorySize, SMEM_TOTAL);

    int blocks = Nn * (HWSZ / 128);   // 2048
    CM_29540785062535_kernel<<<blocks, NTHR, SMEM_TOTAL>>>(
        x, xl, fw, fb, hb, pb, lnw, lnb, out, Nn);
}

// round 14
// speedup vs baseline: 1.2565x; 1.1734x over previous
#include <cuda_runtime.h>

typedef unsigned int u32;
typedef unsigned short u16;

#define CCH  192
#define HWSZ 16384
#define NTHR 256
#define EPSV 1e-6f

// ---- smem byte offsets (per-block 111872 B -> 2 blocks/SM) ----
#define OFF_AH 0u          // A hi: 64px x 192ch bf16, 384B/row, XOR16 swizzle
#define OFF_AL 24576u      // A lo
#define OFF_TH 49152u      // T (q then t) hi  (gate partials overlay early)
#define OFF_TL 73728u      // T lo
#define OFF_W  98304u      // weight k-step stage: 192ch x 16k hi|lo = 12288B
#define OFF_GS 110592u     // gates 3x64 f32 = 768B
#define OFF_MU 111360u     // 64 f32
#define OFF_RS 111616u     // 64 f32
#define SMEM_TOTAL 111872
// py (fp32 y, [ch][64px] stride 256B, swizzled) overlays OFF_AH..49152
// LN partials overlay OFF_W

// 36 regions = 3 gemms x 12 k-steps; each 192 rows x 64B = 12288B. 442368 B.
__device__ __align__(16) u16 g_wc[221184];

__device__ __forceinline__ u32 cvt2(float lo, float hi) {
    u32 r; asm("cvt.rn.bf16x2.f32 %0, %1, %2;" : "=r"(r) : "f"(hi), "f"(lo)); return r;
}
__device__ __forceinline__ void split2(float a, float b, u32& h2, u32& l2) {
    h2 = cvt2(a, b);
    float ah = __uint_as_float(h2 << 16);
    float bh = __uint_as_float(h2 & 0xFFFF0000u);
    l2 = cvt2(a - ah, b - bh);
}
__device__ __forceinline__ u32 smem_u32_of(const void* p) {
    u32 a;
    asm("{ .reg .u64 t; cvta.to.shared.u64 t, %1; cvt.u32.u64 %0, t; }" : "=r"(a) : "l"(p));
    return a;
}
__device__ __forceinline__ void ldsm4(u32& r0, u32& r1, u32& r2, u32& r3, u32 a) {
    asm volatile("ldmatrix.sync.aligned.m8n8.x4.shared.b16 {%0,%1,%2,%3}, [%4];"
                 : "=r"(r0), "=r"(r1), "=r"(r2), "=r"(r3) : "r"(a));
}
__device__ __forceinline__ void mma16816(float* d, u32 a0, u32 a1, u32 a2, u32 a3,
                                         u32 b0, u32 b1) {
    asm volatile(
        "mma.sync.aligned.m16n8k16.row.col.f32.bf16.bf16.f32 "
        "{%0,%1,%2,%3}, {%4,%5,%6,%7}, {%8,%9}, {%0,%1,%2,%3};"
        : "+f"(d[0]), "+f"(d[1]), "+f"(d[2]), "+f"(d[3])
        : "r"(a0), "r"(a1), "r"(a2), "r"(a3), "r"(b0), "r"(b1));
}

// ---- pre-kernel: fp32 weights -> bf16 hi/lo, 36 k-step regions (R10 layout) ----
// 64B row = 4 slots of 16B: slot_h = kk>>3, slot_l = 2+(kk>>3), XOR ((row>>1)&3)
__global__ void CM_wconv_kernel(const float* __restrict__ fw,
                                const float* __restrict__ hwm,
                                const float* __restrict__ pw) {
    int idx = blockIdx.x * 256 + threadIdx.x;
    if (idx >= 3 * 192 * 192) return;
    int g = idx / (192 * 192);
    int rem = idx - g * (192 * 192);
    int r = rem / 192, k = rem - (rem / 192) * 192;
    const float* src = (g == 0) ? fw : (g == 1) ? hwm : pw;
    float w = src[r * 192 + k];
    u32 h2 = cvt2(w, 0.f);
    float hf = __uint_as_float(h2 << 16);
    u32 l2 = cvt2(w - hf, 0.f);
    int region = g * 12 + (k >> 4);
    int kk = k & 15;
    u32 base = (u32)region * 12288u + (u32)r * 64u + (u32)(kk & 7) * 2u;
    u32 sw = ((u32)(r >> 1) & 3u);
    u32 uh = (u32)(kk >> 3);
    u32 ul = uh + 2u;
    g_wc[(base + ((uh ^ sw) << 4)) >> 1] = (u16)(h2 & 0xFFFFu);
    g_wc[(base + ((ul ^ sw) << 4)) >> 1] = (u16)(l2 & 0xFFFFu);
}

// full GEMM over K=192: 12 k-steps, per-step W staging with register ping,
// warp tile Mt=2 (32px) x Nt=6 (48ch), full N=192 in one pass.
__device__ __forceinline__ void gemm_full(char* smem, u32 smb, u32 offH, u32 offL,
                                          int g, float (&acc)[48],
                                          int wm, int wn, int lane, int t) {
    const uint4* gw = (const uint4*)g_wc;   // 768 uint4 per region
    const int gbase = g * 9216;
    uint4 ph0 = gw[gbase + t];
    uint4 ph1 = gw[gbase + t + 256];
    uint4 ph2 = gw[gbase + t + 512];

    const u32 aswz = (u32)(lane & 7) << 4;
    const u32 axor = ((u32)(lane >> 4) & 1u) * 16u;
    const u32 abase = ((u32)(32 * wm) + (u32)(lane & 7) + ((u32)(lane >> 3) & 1u) * 8u) * 384u;
    const u32 abh = smb + offH + abase;
    const u32 abl = smb + offL + abase;
    const u32 uu = ((u32)(lane >> 4) & 1u) * 2u + ((u32)(lane >> 3) & 1u);
    const u32 bb = smb + OFF_W + (u32)(wn * 3072)
                 + (u32)(lane & 7) * 64u + ((uu ^ (((u32)lane >> 1) & 3u)) << 4);

    #pragma unroll 1
    for (int ks = 0; ks < 12; ++ks) {
        ((uint4*)(smem + OFF_W))[t]       = ph0;
        ((uint4*)(smem + OFF_W))[t + 256] = ph1;
        ((uint4*)(smem + OFF_W))[t + 512] = ph2;
        __syncthreads();
        if (ks < 11) {
            int nb = gbase + (ks + 1) * 768;
            ph0 = gw[nb + t];
            ph1 = gw[nb + t + 256];
            ph2 = gw[nb + t + 512];
        }
        u32 acol = (32u * (u32)ks + axor) ^ aswz;
        u32 fa[16];
        ldsm4(fa[0],  fa[1],  fa[2],  fa[3],  abh + acol);
        ldsm4(fa[4],  fa[5],  fa[6],  fa[7],  abl + acol);
        ldsm4(fa[8],  fa[9],  fa[10], fa[11], abh + 6144u + acol);
        ldsm4(fa[12], fa[13], fa[14], fa[15], abl + 6144u + acol);
        u32 fb[24];
        #pragma unroll
        for (int nt = 0; nt < 6; ++nt)
            ldsm4(fb[4*nt+0], fb[4*nt+1], fb[4*nt+2], fb[4*nt+3], bb + (u32)(nt * 512));
        #pragma unroll
        for (int mt = 0; mt < 2; ++mt)
            #pragma unroll
            for (int nt = 0; nt < 6; ++nt) {
                float* a = &acc[(mt * 6 + nt) * 4];
                mma16816(a, fa[8*mt+0], fa[8*mt+1], fa[8*mt+2], fa[8*mt+3],
                         fb[4*nt+0], fb[4*nt+1]);                     // hh
                mma16816(a, fa[8*mt+0], fa[8*mt+1], fa[8*mt+2], fa[8*mt+3],
                         fb[4*nt+2], fb[4*nt+3]);                     // h*lo(B)
                mma16816(a, fa[8*mt+4], fa[8*mt+5], fa[8*mt+6], fa[8*mt+7],
                         fb[4*nt+0], fb[4*nt+1]);                     // lo(A)*h
            }
        __syncthreads();
    }
}

__global__ void __launch_bounds__(NTHR, 2)
CM_29540785062535_kernel(const float* __restrict__ x,
                         const float* __restrict__ xl,
                         const float* __restrict__ fw,
                         const float* __restrict__ fbg,
                         const float* __restrict__ hbg,
                         const float* __restrict__ pbg,
                         const float* __restrict__ lnwg,
                         const float* __restrict__ lnbg,
                         float* __restrict__ out,
                         int Nn)
{
    extern __shared__ char smem[];
    const u32 smb = smem_u32_of(smem);
    const int t    = threadIdx.x;
    const int lane = t & 31;
    const int w    = t >> 5;
    const int wm   = w & 1;        // 2 M positions (32px each)
    const int wn   = w >> 1;       // 4 N positions (48ch each)

    const int n   = blockIdx.x >> 8;        // 256 tiles per image
    const int hw0 = (blockIdx.x & 255) << 6;

    float* gsf = (float*)(smem + OFF_GS);
    float* mus = (float*)(smem + OFF_MU);
    float* rss = (float*)(smem + OFF_RS);

    const int px4 = t & 15;        // pixel quad 0..15
    const int cpb = t >> 4;        // channel-pair group 0..15

    // ---- phase 1: stage x -> AH/AL + gate partials (overlay TH) ----
    {
        const float* xb = x + ((size_t)n * CCH) * HWSZ + hw0;
        float* gpart = (float*)(smem + OFF_TH);
        float ga[12];
        #pragma unroll
        for (int m = 0; m < 12; ++m) ga[m] = 0.f;
        #pragma unroll 2
        for (int j = 0; j < 6; ++j) {
            int cp = cpb + 16 * j;           // 0..95
            int c = 2 * cp;
            float4 a = *(const float4*)(xb + (size_t)c * HWSZ + 4 * px4);
            float4 b = *(const float4*)(xb + (size_t)(c + 1) * HWSZ + 4 * px4);
            float av[4] = {a.x, a.y, a.z, a.w};
            float bv[4] = {b.x, b.y, b.z, b.w};
            #pragma unroll
            for (int jj = 0; jj < 4; ++jj) {
                u32 h2, l2;
                split2(av[jj], bv[jj], h2, l2);
                u32 px = (u32)(4 * px4 + jj);
                u32 off = px * 384u + (((u32)(2 * c)) ^ ((px & 7u) << 4));
                *(u32*)(smem + OFF_AH + off) = h2;
                *(u32*)(smem + OFF_AL + off) = l2;
            }
            #pragma unroll
            for (int l = 0; l < 3; ++l) {
                float w0 = __ldg(fw + (size_t)(192 + l) * 192 + c);
                float w1 = __ldg(fw + (size_t)(192 + l) * 192 + c + 1);
                #pragma unroll
                for (int jj = 0; jj < 4; ++jj)
                    ga[l * 4 + jj] = fmaf(w0, av[jj], fmaf(w1, bv[jj], ga[l * 4 + jj]));
            }
        }
        #pragma unroll
        for (int l = 0; l < 3; ++l)
            #pragma unroll
            for (int jj = 0; jj < 4; ++jj)
                gpart[cpb * 192 + l * 64 + 4 * px4 + jj] = ga[l * 4 + jj];
    }
    __syncthreads();
    if (t < 192) {
        const float* gpart = (const float*)(smem + OFF_TH);
        float v = __ldg(fbg + 192 + (t >> 6));
        #pragma unroll
        for (int g = 0; g < 16; ++g) v += gpart[g * 192 + t];
        gsf[t] = v;
    }
    __syncthreads();

    const int tq = lane & 3;
    const int gg = lane >> 2;

    float acc[48];

    // ---- GEMM1: q = x @ fw ; q+fb -> TH/TL ----
    #pragma unroll
    for (int m = 0; m < 48; ++m) acc[m] = 0.f;
    gemm_full(smem, smb, OFF_AH, OFF_AL, 0, acc, wm, wn, lane, t);
    #pragma unroll
    for (int mt = 0; mt < 2; ++mt)
        #pragma unroll
        for (int nt = 0; nt < 6; ++nt) {
            int ch0 = 48 * wn + 8 * nt + 2 * tq;
            int r0 = 32 * wm + 16 * mt + gg;
            const float* a = &acc[(mt * 6 + nt) * 4];
            float f0 = __ldg(fbg + ch0), f1 = __ldg(fbg + ch0 + 1);
            u32 o0 = (u32)r0 * 384u + (((u32)(2 * ch0)) ^ (((u32)r0 & 7u) << 4));
            u32 o1 = o0 + 8u * 384u;
            u32 h2, l2;
            split2(a[0] + f0, a[1] + f1, h2, l2);
            *(u32*)(smem + OFF_TH + o0) = h2;
            *(u32*)(smem + OFF_TL + o0) = l2;
            split2(a[2] + f0, a[3] + f1, h2, l2);
            *(u32*)(smem + OFF_TH + o1) = h2;
            *(u32*)(smem + OFF_TL + o1) = l2;
        }

    // ---- ctx = sum_l gates[l]*x_list[l] -> AH/AL ----
    // (A fully read before gemm_full's final sync; GEMM2's first stage sync
    //  publishes these writes before any warp ldsm's them)
    {
        const float* b0 = xl + ((size_t)(0 * Nn + n) * CCH) * HWSZ + hw0;
        const float* b1 = xl + ((size_t)(1 * Nn + n) * CCH) * HWSZ + hw0;
        const float* b2 = xl + ((size_t)(2 * Nn + n) * CCH) * HWSZ + hw0;
        float4 g0 = *(const float4*)(gsf + 0 * 64 + 4 * px4);
        float4 g1 = *(const float4*)(gsf + 1 * 64 + 4 * px4);
        float4 g2 = *(const float4*)(gsf + 2 * 64 + 4 * px4);
        float g0v[4] = {g0.x, g0.y, g0.z, g0.w};
        float g1v[4] = {g1.x, g1.y, g1.z, g1.w};
        float g2v[4] = {g2.x, g2.y, g2.z, g2.w};
        #pragma unroll 2
        for (int j = 0; j < 6; ++j) {
            int cp = cpb + 16 * j;
            int c = 2 * cp;
            size_t oa = (size_t)c * HWSZ + 4 * px4;
            size_t ob = oa + HWSZ;
            float4 a0 = *(const float4*)(b0 + oa), a1 = *(const float4*)(b1 + oa), a2 = *(const float4*)(b2 + oa);
            float4 c0 = *(const float4*)(b0 + ob), c1 = *(const float4*)(b1 + ob), c2 = *(const float4*)(b2 + ob);
            float a0v[4] = {a0.x, a0.y, a0.z, a0.w};
            float a1v[4] = {a1.x, a1.y, a1.z, a1.w};
            float a2v[4] = {a2.x, a2.y, a2.z, a2.w};
            float c0v[4] = {c0.x, c0.y, c0.z, c0.w};
            float c1v[4] = {c1.x, c1.y, c1.z, c1.w};
            float c2v[4] = {c2.x, c2.y, c2.z, c2.w};
            #pragma unroll
            for (int jj = 0; jj < 4; ++jj) {
                float va = fmaf(g2v[jj], a2v[jj], fmaf(g1v[jj], a1v[jj], g0v[jj] * a0v[jj]));
                float vb = fmaf(g2v[jj], c2v[jj], fmaf(g1v[jj], c1v[jj], g0v[jj] * c0v[jj]));
                u32 h2, l2;
                split2(va, vb, h2, l2);
                u32 px = (u32)(4 * px4 + jj);
                u32 off = px * 384u + (((u32)(2 * c)) ^ ((px & 7u) << 4));
                *(u32*)(smem + OFF_AH + off) = h2;
                *(u32*)(smem + OFF_AL + off) = l2;
            }
        }
    }
    __syncthreads();

    // ---- GEMM2: mod = ctx @ hw ; t = q*(mod+hb) -> TH/TL in place ----
    #pragma unroll
    for (int m = 0; m < 48; ++m) acc[m] = 0.f;
    gemm_full(smem, smb, OFF_AH, OFF_AL, 1, acc, wm, wn, lane, t);
    #pragma unroll
    for (int mt = 0; mt < 2; ++mt)
        #pragma unroll
        for (int nt = 0; nt < 6; ++nt) {
            int ch0 = 48 * wn + 8 * nt + 2 * tq;
            int r0 = 32 * wm + 16 * mt + gg;
            const float* a = &acc[(mt * 6 + nt) * 4];
            float h0 = __ldg(hbg + ch0), h1 = __ldg(hbg + ch0 + 1);
            u32 o0 = (u32)r0 * 384u + (((u32)(2 * ch0)) ^ (((u32)r0 & 7u) << 4));
            u32 o1 = o0 + 8u * 384u;
            u32 qh = *(u32*)(smem + OFF_TH + o0);
            u32 ql = *(u32*)(smem + OFF_TL + o0);
            float q0 = __uint_as_float(qh << 16) + __uint_as_float(ql << 16);
            float q1 = __uint_as_float(qh & 0xFFFF0000u) + __uint_as_float(ql & 0xFFFF0000u);
            float t0 = q0 * (a[0] + h0);
            float t1 = q1 * (a[1] + h1);
            u32 h2, l2;
            split2(t0, t1, h2, l2);
            *(u32*)(smem + OFF_TH + o0) = h2;
            *(u32*)(smem + OFF_TL + o0) = l2;
            qh = *(u32*)(smem + OFF_TH + o1);
            ql = *(u32*)(smem + OFF_TL + o1);
            q0 = __uint_as_float(qh << 16) + __uint_as_float(ql << 16);
            q1 = __uint_as_float(qh & 0xFFFF0000u) + __uint_as_float(ql & 0xFFFF0000u);
            t0 = q0 * (a[2] + h0);
            t1 = q1 * (a[3] + h1);
            split2(t0, t1, h2, l2);
            *(u32*)(smem + OFF_TH + o1) = h2;
            *(u32*)(smem + OFF_TL + o1) = l2;
        }
    __syncthreads();   // t fully written before GEMM3 reads it as A

    // ---- GEMM3: y = t @ pw ; y+pb -> py fp32 [ch][64px] (overlays A) ----
    #pragma unroll
    for (int m = 0; m < 48; ++m) acc[m] = 0.f;
    gemm_full(smem, smb, OFF_TH, OFF_TL, 2, acc, wm, wn, lane, t);
    #pragma unroll
    for (int mt = 0; mt < 2; ++mt)
        #pragma unroll
        for (int nt = 0; nt < 6; ++nt) {
            int ch0 = 48 * wn + 8 * nt + 2 * tq;
            int r0 = 32 * wm + 16 * mt + gg;
            int r1 = r0 + 8;
            const float* a = &acc[(mt * 6 + nt) * 4];
            float p0 = __ldg(pbg + ch0), p1 = __ldg(pbg + ch0 + 1);
            u32 s0 = (u32)ch0 * 256u + (((u32)(4 * r0)) ^ (((u32)ch0 & 7u) << 4));
            u32 s1 = (u32)(ch0 + 1) * 256u + (((u32)(4 * r0)) ^ (((u32)(ch0 + 1) & 7u) << 4));
            u32 s2 = (u32)ch0 * 256u + (((u32)(4 * r1)) ^ (((u32)ch0 & 7u) << 4));
            u32 s3 = (u32)(ch0 + 1) * 256u + (((u32)(4 * r1)) ^ (((u32)(ch0 + 1) & 7u) << 4));
            *(float*)(smem + s0) = a[0] + p0;
            *(float*)(smem + s1) = a[1] + p1;
            *(float*)(smem + s2) = a[2] + p0;
            *(float*)(smem + s3) = a[3] + p1;
        }
    __syncthreads();

    // ---- LN stats: 4 segs x 64 px (partials overlay W) ----
    {
        float* ps = (float*)(smem + OFF_W);
        float* qs = ps + 256;
        int seg = t >> 6, px = t & 63;
        float s = 0.f, s2 = 0.f;
        #pragma unroll 4
        for (int ch = 48 * seg; ch < 48 * seg + 48; ++ch) {
            float v = *(float*)(smem + (u32)ch * 256u + (((u32)(4 * px)) ^ (((u32)ch & 7u) << 4)));
            s += v;
            s2 = fmaf(v, v, s2);
        }
        ps[t] = s; qs[t] = s2;
    }
    __syncthreads();
    if (t < 64) {
        float* ps = (float*)(smem + OFF_W);
        float* qs = ps + 256;
        float st = (ps[t] + ps[t + 64]) + (ps[t + 128] + ps[t + 192]);
        float qt = (qs[t] + qs[t + 64]) + (qs[t + 128] + qs[t + 192]);
        float mu  = st * (1.0f / CCH);
        float var = qt * (1.0f / CCH) - mu * mu;
        mus[t] = mu;
        rss[t] = rsqrtf(var + EPSV);
    }
    __syncthreads();

    // ---- normalize + residual + coalesced store (x reloaded from HBM) ----
    {
        const float* xb = x + ((size_t)n * CCH) * HWSZ + hw0;
        float* ob = out + ((size_t)n * CCH) * HWSZ + hw0;
        #pragma unroll 4
        for (int u = 0; u < 12; ++u) {
            int f4 = t + 256 * u;            // 192ch x 16 quads = 3072
            int c = f4 >> 4, L = f4 & 15;
            float4 y = *(const float4*)(smem + (u32)c * 256u + (((u32)(16 * L)) ^ (((u32)c & 7u) << 4)));
            float4 xv = *(const float4*)(xb + (size_t)c * HWSZ + 4 * L);
            float4 m = *(const float4*)(mus + 4 * L);
            float4 r = *(const float4*)(rss + 4 * L);
            float lw = __ldg(lnwg + c), lb = __ldg(lnbg + c);
            float4 o;
            o.x = fmaf(lw * (y.x - m.x), r.x, lb) + xv.x;
            o.y = fmaf(lw * (y.y - m.y), r.y, lb) + xv.y;
            o.z = fmaf(lw * (y.z - m.z), r.z, lb) + xv.z;
            o.w = fmaf(lw * (y.w - m.w), r.w, lb) + xv.w;
            *(float4*)(ob + (size_t)c * HWSZ + 4 * L) = o;
        }
    }
}

extern "C" void kernel_launch(void* const* d_in, const int* in_sizes, int n_in,
                              void* d_out, int out_size) {
    const float* x   = (const float*)d_in[0];
    const float* xl  = (const float*)d_in[1];
    const float* fw  = (const float*)d_in[2];
    const float* fb  = (const float*)d_in[3];
    const float* hwm = (const float*)d_in[4];
    const float* hb  = (const float*)d_in[5];
    const float* pw  = (const float*)d_in[6];
    const float* pb  = (const float*)d_in[7];
    const float* lnw = (const float*)d_in[8];
    const float* lnb = (const float*)d_in[9];
    float* out = (float*)d_out;

    int Nn = in_sizes[0] / (CCH * HWSZ);

    CM_wconv_kernel<<<(3 * 192 * 192 + 255) / 256, 256>>>(fw, hwm, pw);

    cudaFuncSetAttribute(CM_29540785062535_kernel,
                         cudaFuncAttributeMaxDynamicSharedMemorySize, SMEM_TOTAL);

    int blocks = Nn * (HWSZ / 64);   // 16 * 256 = 4096
    CM_29540785062535_kernel<<<blocks, NTHR, SMEM_TOTAL>>>(
        x, xl, fw, fb, hb, pb, lnw, lnb, out, Nn);
}

// round 15
// speedup vs baseline: 1.3513x; 1.0755x over previous
#include <cuda_runtime.h>

typedef unsigned int u32;
typedef unsigned short u16;

#define CCH  192
#define HWSZ 16384
#define NTHR 256
#define EPSV 1e-6f

// ---- smem byte offsets (per-block 111872 B -> 2 blocks/SM) ----
#define OFF_AH 0u          // A hi: 64px x 192ch bf16, 384B/row, XOR16 swizzle
#define OFF_AL 24576u      // A lo
#define OFF_TH 49152u      // T (q then t) hi  (gate partials overlay early; W pipe buf in GEMM1)
#define OFF_TL 73728u      // T lo                                (W pipe buf in GEMM1)
#define OFF_W  98304u      // weight k-step stage: 192ch x 16k hi|lo = 12288B
#define OFF_GS 110592u     // gates 3x64 f32
#define OFF_MU 111360u
#define OFF_RS 111616u
#define SMEM_TOTAL 111872
// py (fp32 y, [ch][64px] stride 256B, swizzled) overlays OFF_AH..49152
// LN partials overlay OFF_W

// 36 regions = 3 gemms x 12 k-steps; each 192 rows x 64B = 12288B. 442368 B.
__device__ __align__(16) u16 g_wc[221184];

#define CPA(dst, src) asm volatile("cp.async.cg.shared.global [%0], [%1], 16;" :: "r"(dst), "l"(src) : "memory")
#define CPC()         asm volatile("cp.async.commit_group;" ::: "memory")
#define CPW0()        asm volatile("cp.async.wait_group 0;" ::: "memory")
#define CPW1()        asm volatile("cp.async.wait_group 1;" ::: "memory")

__device__ __forceinline__ u32 cvt2(float lo, float hi) {
    u32 r; asm("cvt.rn.bf16x2.f32 %0, %1, %2;" : "=r"(r) : "f"(hi), "f"(lo)); return r;
}
__device__ __forceinline__ void split2(float a, float b, u32& h2, u32& l2) {
    h2 = cvt2(a, b);
    float ah = __uint_as_float(h2 << 16);
    float bh = __uint_as_float(h2 & 0xFFFF0000u);
    l2 = cvt2(a - ah, b - bh);
}
__device__ __forceinline__ u32 smem_u32_of(const void* p) {
    u32 a;
    asm("{ .reg .u64 t; cvta.to.shared.u64 t, %1; cvt.u32.u64 %0, t; }" : "=r"(a) : "l"(p));
    return a;
}
__device__ __forceinline__ void ldsm4(u32& r0, u32& r1, u32& r2, u32& r3, u32 a) {
    asm volatile("ldmatrix.sync.aligned.m8n8.x4.shared.b16 {%0,%1,%2,%3}, [%4];"
                 : "=r"(r0), "=r"(r1), "=r"(r2), "=r"(r3) : "r"(a));
}
__device__ __forceinline__ void mma16816(float* d, u32 a0, u32 a1, u32 a2, u32 a3,
                                         u32 b0, u32 b1) {
    asm volatile(
        "mma.sync.aligned.m16n8k16.row.col.f32.bf16.bf16.f32 "
        "{%0,%1,%2,%3}, {%4,%5,%6,%7}, {%8,%9}, {%0,%1,%2,%3};"
        : "+f"(d[0]), "+f"(d[1]), "+f"(d[2]), "+f"(d[3])
        : "r"(a0), "r"(a1), "r"(a2), "r"(a3), "r"(b0), "r"(b1));
}

// ---- pre-kernel: fp32 weights -> bf16 hi/lo, 36 k-step regions ----
// 64B row = 4 slots of 16B: slot_h = kk>>3, slot_l = 2+(kk>>3), XOR ((row>>1)&3)
__global__ void CM_wconv_kernel(const float* __restrict__ fw,
                                const float* __restrict__ hwm,
                                const float* __restrict__ pw) {
    int idx = blockIdx.x * 256 + threadIdx.x;
    if (idx >= 3 * 192 * 192) return;
    int g = idx / (192 * 192);
    int rem = idx - g * (192 * 192);
    int r = rem / 192, k = rem - (rem / 192) * 192;
    const float* src = (g == 0) ? fw : (g == 1) ? hwm : pw;
    float w = src[r * 192 + k];
    u32 h2 = cvt2(w, 0.f);
    float hf = __uint_as_float(h2 << 16);
    u32 l2 = cvt2(w - hf, 0.f);
    int region = g * 12 + (k >> 4);
    int kk = k & 15;
    u32 base = (u32)region * 12288u + (u32)r * 64u + (u32)(kk & 7) * 2u;
    u32 sw = ((u32)(r >> 1) & 3u);
    u32 uh = (u32)(kk >> 3);
    u32 ul = uh + 2u;
    g_wc[(base + ((uh ^ sw) << 4)) >> 1] = (u16)(h2 & 0xFFFFu);
    g_wc[(base + ((ul ^ sw) << 4)) >> 1] = (u16)(l2 & 0xFFFFu);
}

__device__ __forceinline__ void stage_async(u32 dst, const char* src, int t) {
    #pragma unroll
    for (int j = 0; j < 3; ++j)
        CPA(dst + (u32)t * 16u + (u32)j * 4096u, src + t * 16 + j * 4096);
    CPC();
}

// pipelined GEMM (GEMM1/GEMM3): 3 rotating W buffers, 1 sync per k-step
__device__ __forceinline__ void gemm_pipe(u32 smb, u32 offH, u32 offL, int g,
                                          u32 cur0, u32 cur1, u32 cur2,
                                          float (&acc)[48],
                                          int wm, int wn, int lane, int t) {
    const char* gbase = (const char*)g_wc + (size_t)g * 147456;
    stage_async(cur0, gbase, t);
    stage_async(cur1, gbase + 12288, t);

    const u32 aswz = (u32)(lane & 7) << 4;
    const u32 axor = ((u32)(lane >> 4) & 1u) * 16u;
    const u32 abase = ((u32)(32 * wm) + (u32)(lane & 7) + ((u32)(lane >> 3) & 1u) * 8u) * 384u;
    const u32 abh = smb + offH + abase;
    const u32 abl = smb + offL + abase;
    const u32 uu = ((u32)(lane >> 4) & 1u) * 2u + ((u32)(lane >> 3) & 1u);
    const u32 bloff = (u32)(wn * 3072)
                    + (u32)(lane & 7) * 64u + ((uu ^ (((u32)lane >> 1) & 3u)) << 4);

    #pragma unroll 1
    for (int ks = 0; ks < 12; ++ks) {
        if (ks == 11) { CPW0(); } else { CPW1(); }
        __syncthreads();
        if (ks < 10) stage_async(cur2, gbase + (size_t)(ks + 2) * 12288, t);
        u32 acol = (32u * (u32)ks + axor) ^ aswz;
        u32 fa[16];
        ldsm4(fa[0],  fa[1],  fa[2],  fa[3],  abh + acol);
        ldsm4(fa[4],  fa[5],  fa[6],  fa[7],  abl + acol);
        ldsm4(fa[8],  fa[9],  fa[10], fa[11], abh + 6144u + acol);
        ldsm4(fa[12], fa[13], fa[14], fa[15], abl + 6144u + acol);
        u32 fb[24];
        u32 bb = cur0 + bloff;
        #pragma unroll
        for (int nt = 0; nt < 6; ++nt)
            ldsm4(fb[4*nt+0], fb[4*nt+1], fb[4*nt+2], fb[4*nt+3], bb + (u32)(nt * 512));
        #pragma unroll
        for (int mt = 0; mt < 2; ++mt)
            #pragma unroll
            for (int nt = 0; nt < 6; ++nt) {
                float* a = &acc[(mt * 6 + nt) * 4];
                mma16816(a, fa[8*mt+0], fa[8*mt+1], fa[8*mt+2], fa[8*mt+3],
                         fb[4*nt+0], fb[4*nt+1]);                     // hh
                mma16816(a, fa[8*mt+0], fa[8*mt+1], fa[8*mt+2], fa[8*mt+3],
                         fb[4*nt+2], fb[4*nt+3]);                     // h*lo(B)
                mma16816(a, fa[8*mt+4], fa[8*mt+5], fa[8*mt+6], fa[8*mt+7],
                         fb[4*nt+0], fb[4*nt+1]);                     // lo(A)*h
            }
        u32 tmp = cur0; cur0 = cur1; cur1 = cur2; cur2 = tmp;
    }
    __syncthreads();   // all MMAs done before caller overwrites pipe buffers
}

// single-buffer GEMM (GEMM2): R14 register-ping scheme, 2 syncs per k-step
__device__ __forceinline__ void gemm_single(char* smem, u32 smb, u32 offH, u32 offL,
                                            int g, float (&acc)[48],
                                            int wm, int wn, int lane, int t) {
    const uint4* gw = (const uint4*)g_wc;
    const int gbase = g * 9216;
    uint4 ph0 = gw[gbase + t];
    uint4 ph1 = gw[gbase + t + 256];
    uint4 ph2 = gw[gbase + t + 512];

    const u32 aswz = (u32)(lane & 7) << 4;
    const u32 axor = ((u32)(lane >> 4) & 1u) * 16u;
    const u32 abase = ((u32)(32 * wm) + (u32)(lane & 7) + ((u32)(lane >> 3) & 1u) * 8u) * 384u;
    const u32 abh = smb + offH + abase;
    const u32 abl = smb + offL + abase;
    const u32 uu = ((u32)(lane >> 4) & 1u) * 2u + ((u32)(lane >> 3) & 1u);
    const u32 bb = smb + OFF_W + (u32)(wn * 3072)
                 + (u32)(lane & 7) * 64u + ((uu ^ (((u32)lane >> 1) & 3u)) << 4);

    #pragma unroll 1
    for (int ks = 0; ks < 12; ++ks) {
        ((uint4*)(smem + OFF_W))[t]       = ph0;
        ((uint4*)(smem + OFF_W))[t + 256] = ph1;
        ((uint4*)(smem + OFF_W))[t + 512] = ph2;
        __syncthreads();
        if (ks < 11) {
            int nb = gbase + (ks + 1) * 768;
            ph0 = gw[nb + t];
            ph1 = gw[nb + t + 256];
            ph2 = gw[nb + t + 512];
        }
        u32 acol = (32u * (u32)ks + axor) ^ aswz;
        u32 fa[16];
        ldsm4(fa[0],  fa[1],  fa[2],  fa[3],  abh + acol);
        ldsm4(fa[4],  fa[5],  fa[6],  fa[7],  abl + acol);
        ldsm4(fa[8],  fa[9],  fa[10], fa[11], abh + 6144u + acol);
        ldsm4(fa[12], fa[13], fa[14], fa[15], abl + 6144u + acol);
        u32 fb[24];
        #pragma unroll
        for (int nt = 0; nt < 6; ++nt)
            ldsm4(fb[4*nt+0], fb[4*nt+1], fb[4*nt+2], fb[4*nt+3], bb + (u32)(nt * 512));
        #pragma unroll
        for (int mt = 0; mt < 2; ++mt)
            #pragma unroll
            for (int nt = 0; nt < 6; ++nt) {
                float* a = &acc[(mt * 6 + nt) * 4];
                mma16816(a, fa[8*mt+0], fa[8*mt+1], fa[8*mt+2], fa[8*mt+3],
                         fb[4*nt+0], fb[4*nt+1]);
                mma16816(a, fa[8*mt+0], fa[8*mt+1], fa[8*mt+2], fa[8*mt+3],
                         fb[4*nt+2], fb[4*nt+3]);
                mma16816(a, fa[8*mt+4], fa[8*mt+5], fa[8*mt+6], fa[8*mt+7],
                         fb[4*nt+0], fb[4*nt+1]);
            }
        __syncthreads();
    }
}

__global__ void __launch_bounds__(NTHR, 2)
CM_29540785062535_kernel(const float* __restrict__ x,
                         const float* __restrict__ xl,
                         const float* __restrict__ fw,
                         const float* __restrict__ fbg,
                         const float* __restrict__ hbg,
                         const float* __restrict__ pbg,
                         const float* __restrict__ lnwg,
                         const float* __restrict__ lnbg,
                         float* __restrict__ out,
                         int Nn)
{
    extern __shared__ char smem[];
    const u32 smb = smem_u32_of(smem);
    const int t    = threadIdx.x;
    const int lane = t & 31;
    const int w    = t >> 5;
    const int wm   = w & 1;        // 2 M positions (32px each)
    const int wn   = w >> 1;       // 4 N positions (48ch each)

    const int n   = blockIdx.x >> 8;
    const int hw0 = (blockIdx.x & 255) << 6;

    float* gsf = (float*)(smem + OFF_GS);
    float* mus = (float*)(smem + OFF_MU);
    float* rss = (float*)(smem + OFF_RS);

    const int px4 = t & 15;
    const int cpb = t >> 4;

    // ---- phase 1: stage x -> AH/AL + gate partials (overlay TH) ----
    {
        const float* xb = x + ((size_t)n * CCH) * HWSZ + hw0;
        float* gpart = (float*)(smem + OFF_TH);
        float ga[12];
        #pragma unroll
        for (int m = 0; m < 12; ++m) ga[m] = 0.f;
        #pragma unroll 2
        for (int j = 0; j < 6; ++j) {
            int cp = cpb + 16 * j;
            int c = 2 * cp;
            float4 a = *(const float4*)(xb + (size_t)c * HWSZ + 4 * px4);
            float4 b = *(const float4*)(xb + (size_t)(c + 1) * HWSZ + 4 * px4);
            float av[4] = {a.x, a.y, a.z, a.w};
            float bv[4] = {b.x, b.y, b.z, b.w};
            #pragma unroll
            for (int jj = 0; jj < 4; ++jj) {
                u32 h2, l2;
                split2(av[jj], bv[jj], h2, l2);
                u32 px = (u32)(4 * px4 + jj);
                u32 off = px * 384u + (((u32)(2 * c)) ^ ((px & 7u) << 4));
                *(u32*)(smem + OFF_AH + off) = h2;
                *(u32*)(smem + OFF_AL + off) = l2;
            }
            #pragma unroll
            for (int l = 0; l < 3; ++l) {
                float w0 = __ldg(fw + (size_t)(192 + l) * 192 + c);
                float w1 = __ldg(fw + (size_t)(192 + l) * 192 + c + 1);
                #pragma unroll
                for (int jj = 0; jj < 4; ++jj)
                    ga[l * 4 + jj] = fmaf(w0, av[jj], fmaf(w1, bv[jj], ga[l * 4 + jj]));
            }
        }
        #pragma unroll
        for (int l = 0; l < 3; ++l)
            #pragma unroll
            for (int jj = 0; jj < 4; ++jj)
                gpart[cpb * 192 + l * 64 + 4 * px4 + jj] = ga[l * 4 + jj];
    }
    __syncthreads();
    if (t < 192) {
        const float* gpart = (const float*)(smem + OFF_TH);
        float v = __ldg(fbg + 192 + (t >> 6));
        #pragma unroll
        for (int g = 0; g < 16; ++g) v += gpart[g * 192 + t];
        gsf[t] = v;
    }
    __syncthreads();

    const int tq = lane & 3;
    const int gg = lane >> 2;

    float acc[48];

    // ---- GEMM1: q = x @ fw ; q+fb -> TH/TL (pipe bufs: W, TH, TL) ----
    #pragma unroll
    for (int m = 0; m < 48; ++m) acc[m] = 0.f;
    gemm_pipe(smb, OFF_AH, OFF_AL, 0, smb + OFF_W, smb + OFF_TH, smb + OFF_TL,
              acc, wm, wn, lane, t);
    #pragma unroll
    for (int mt = 0; mt < 2; ++mt)
        #pragma unroll
        for (int nt = 0; nt < 6; ++nt) {
            int ch0 = 48 * wn + 8 * nt + 2 * tq;
            int r0 = 32 * wm + 16 * mt + gg;
            const float* a = &acc[(mt * 6 + nt) * 4];
            float f0 = __ldg(fbg + ch0), f1 = __ldg(fbg + ch0 + 1);
            u32 o0 = (u32)r0 * 384u + (((u32)(2 * ch0)) ^ (((u32)r0 & 7u) << 4));
            u32 o1 = o0 + 8u * 384u;
            u32 h2, l2;
            split2(a[0] + f0, a[1] + f1, h2, l2);
            *(u32*)(smem + OFF_TH + o0) = h2;
            *(u32*)(smem + OFF_TL + o0) = l2;
            split2(a[2] + f0, a[3] + f1, h2, l2);
            *(u32*)(smem + OFF_TH + o1) = h2;
            *(u32*)(smem + OFF_TL + o1) = l2;
        }

    // ---- ctx = sum_l gates[l]*x_list[l] -> AH/AL ----
    {
        const float* b0 = xl + ((size_t)(0 * Nn + n) * CCH) * HWSZ + hw0;
        const float* b1 = xl + ((size_t)(1 * Nn + n) * CCH) * HWSZ + hw0;
        const float* b2 = xl + ((size_t)(2 * Nn + n) * CCH) * HWSZ + hw0;
        float4 g0 = *(const float4*)(gsf + 0 * 64 + 4 * px4);
        float4 g1 = *(const float4*)(gsf + 1 * 64 + 4 * px4);
        float4 g2 = *(const float4*)(gsf + 2 * 64 + 4 * px4);
        float g0v[4] = {g0.x, g0.y, g0.z, g0.w};
        float g1v[4] = {g1.x, g1.y, g1.z, g1.w};
        float g2v[4] = {g2.x, g2.y, g2.z, g2.w};
        #pragma unroll 2
        for (int j = 0; j < 6; ++j) {
            int cp = cpb + 16 * j;
            int c = 2 * cp;
            size_t oa = (size_t)c * HWSZ + 4 * px4;
            size_t ob = oa + HWSZ;
            float4 a0 = *(const float4*)(b0 + oa), a1 = *(const float4*)(b1 + oa), a2 = *(const float4*)(b2 + oa);
            float4 c0 = *(const float4*)(b0 + ob), c1 = *(const float4*)(b1 + ob), c2 = *(const float4*)(b2 + ob);
            float a0v[4] = {a0.x, a0.y, a0.z, a0.w};
            float a1v[4] = {a1.x, a1.y, a1.z, a1.w};
            float a2v[4] = {a2.x, a2.y, a2.z, a2.w};
            float c0v[4] = {c0.x, c0.y, c0.z, c0.w};
            float c1v[4] = {c1.x, c1.y, c1.z, c1.w};
            float c2v[4] = {c2.x, c2.y, c2.z, c2.w};
            #pragma unroll
            for (int jj = 0; jj < 4; ++jj) {
                float va = fmaf(g2v[jj], a2v[jj], fmaf(g1v[jj], a1v[jj], g0v[jj] * a0v[jj]));
                float vb = fmaf(g2v[jj], c2v[jj], fmaf(g1v[jj], c1v[jj], g0v[jj] * c0v[jj]));
                u32 h2, l2;
                split2(va, vb, h2, l2);
                u32 px = (u32)(4 * px4 + jj);
                u32 off = px * 384u + (((u32)(2 * c)) ^ ((px & 7u) << 4));
                *(u32*)(smem + OFF_AH + off) = h2;
                *(u32*)(smem + OFF_AL + off) = l2;
            }
        }
    }
    __syncthreads();

    // ---- GEMM2: mod = ctx @ hw ; t = q*(mod+hb) -> TH/TL in place ----
    #pragma unroll
    for (int m = 0; m < 48; ++m) acc[m] = 0.f;
    gemm_single(smem, smb, OFF_AH, OFF_AL, 1, acc, wm, wn, lane, t);
    #pragma unroll
    for (int mt = 0; mt < 2; ++mt)
        #pragma unroll
        for (int nt = 0; nt < 6; ++nt) {
            int ch0 = 48 * wn + 8 * nt + 2 * tq;
            int r0 = 32 * wm + 16 * mt + gg;
            const float* a = &acc[(mt * 6 + nt) * 4];
            float h0 = __ldg(hbg + ch0), h1 = __ldg(hbg + ch0 + 1);
            u32 o0 = (u32)r0 * 384u + (((u32)(2 * ch0)) ^ (((u32)r0 & 7u) << 4));
            u32 o1 = o0 + 8u * 384u;
            u32 qh = *(u32*)(smem + OFF_TH + o0);
            u32 ql = *(u32*)(smem + OFF_TL + o0);
            float q0 = __uint_as_float(qh << 16) + __uint_as_float(ql << 16);
            float q1 = __uint_as_float(qh & 0xFFFF0000u) + __uint_as_float(ql & 0xFFFF0000u);
            float t0 = q0 * (a[0] + h0);
            float t1 = q1 * (a[1] + h1);
            u32 h2, l2;
            split2(t0, t1, h2, l2);
            *(u32*)(smem + OFF_TH + o0) = h2;
            *(u32*)(smem + OFF_TL + o0) = l2;
            qh = *(u32*)(smem + OFF_TH + o1);
            ql = *(u32*)(smem + OFF_TL + o1);
            q0 = __uint_as_float(qh << 16) + __uint_as_float(ql << 16);
            q1 = __uint_as_float(qh & 0xFFFF0000u) + __uint_as_float(ql & 0xFFFF0000u);
            t0 = q0 * (a[2] + h0);
            t1 = q1 * (a[3] + h1);
            split2(t0, t1, h2, l2);
            *(u32*)(smem + OFF_TH + o1) = h2;
            *(u32*)(smem + OFF_TL + o1) = l2;
        }
    // (gemm_pipe's first wait+sync publishes t before any ldsm of TH/TL)

    // ---- GEMM3: y = t @ pw ; y+pb -> py fp32 (pipe bufs: W, AH, AL) ----
    #pragma unroll
    for (int m = 0; m < 48; ++m) acc[m] = 0.f;
    gemm_pipe(smb, OFF_TH, OFF_TL, 2, smb + OFF_W, smb + OFF_AH, smb + OFF_AL,
              acc, wm, wn, lane, t);
    #pragma unroll
    for (int mt = 0; mt < 2; ++mt)
        #pragma unroll
        for (int nt = 0; nt < 6; ++nt) {
            int ch0 = 48 * wn + 8 * nt + 2 * tq;
            int r0 = 32 * wm + 16 * mt + gg;
            int r1 = r0 + 8;
            const float* a = &acc[(mt * 6 + nt) * 4];
            float p0 = __ldg(pbg + ch0), p1 = __ldg(pbg + ch0 + 1);
            u32 s0 = (u32)ch0 * 256u + (((u32)(4 * r0)) ^ (((u32)ch0 & 7u) << 4));
            u32 s1 = (u32)(ch0 + 1) * 256u + (((u32)(4 * r0)) ^ (((u32)(ch0 + 1) & 7u) << 4));
            u32 s2 = (u32)ch0 * 256u + (((u32)(4 * r1)) ^ (((u32)ch0 & 7u) << 4));
            u32 s3 = (u32)(ch0 + 1) * 256u + (((u32)(4 * r1)) ^ (((u32)(ch0 + 1) & 7u) << 4));
            *(float*)(smem + s0) = a[0] + p0;
            *(float*)(smem + s1) = a[1] + p1;
            *(float*)(smem + s2) = a[2] + p0;
            *(float*)(smem + s3) = a[3] + p1;
        }
    __syncthreads();

    // ---- LN stats: 4 segs x 64 px (partials overlay W) ----
    {
        float* ps = (float*)(smem + OFF_W);
        float* qs = ps + 256;
        int seg = t >> 6, px = t & 63;
        float s = 0.f, s2 = 0.f;
        #pragma unroll 4
        for (int ch = 48 * seg; ch < 48 * seg + 48; ++ch) {
            float v = *(float*)(smem + (u32)ch * 256u + (((u32)(4 * px)) ^ (((u32)ch & 7u) << 4)));
            s += v;
            s2 = fmaf(v, v, s2);
        }
        ps[t] = s; qs[t] = s2;
    }
    __syncthreads();
    if (t < 64) {
        float* ps = (float*)(smem + OFF_W);
        float* qs = ps + 256;
        float st = (ps[t] + ps[t + 64]) + (ps[t + 128] + ps[t + 192]);
        float qt = (qs[t] + qs[t + 64]) + (qs[t + 128] + qs[t + 192]);
        float mu  = st * (1.0f / CCH);
        float var = qt * (1.0f / CCH) - mu * mu;
        mus[t] = mu;
        rss[t] = rsqrtf(var + EPSV);
    }
    __syncthreads();

    // ---- normalize + residual + coalesced store (x reloaded from HBM) ----
    {
        const float* xb = x + ((size_t)n * CCH) * HWSZ + hw0;
        float* ob = out + ((size_t)n * CCH) * HWSZ + hw0;
        #pragma unroll 4
        for (int u = 0; u < 12; ++u) {
            int f4 = t + 256 * u;
            int c = f4 >> 4, L = f4 & 15;
            float4 y = *(const float4*)(smem + (u32)c * 256u + (((u32)(16 * L)) ^ (((u32)c & 7u) << 4)));
            float4 xv = *(const float4*)(xb + (size_t)c * HWSZ + 4 * L);
            float4 m = *(const float4*)(mus + 4 * L);
            float4 r = *(const float4*)(rss + 4 * L);
            float lw = __ldg(lnwg + c), lb = __ldg(lnbg + c);
            float4 o;
            o.x = fmaf(lw * (y.x - m.x), r.x, lb) + xv.x;
            o.y = fmaf(lw * (y.y - m.y), r.y, lb) + xv.y;
            o.z = fmaf(lw * (y.z - m.z), r.z, lb) + xv.z;
            o.w = fmaf(lw * (y.w - m.w), r.w, lb) + xv.w;
            *(float4*)(ob + (size_t)c * HWSZ + 4 * L) = o;
        }
    }
}

extern "C" void kernel_launch(void* const* d_in, const int* in_sizes, int n_in,
                              void* d_out, int out_size) {
    const float* x   = (const float*)d_in[0];
    const float* xl  = (const float*)d_in[1];
    const float* fw  = (const float*)d_in[2];
    const float* fb  = (const float*)d_in[3];
    const float* hwm = (const float*)d_in[4];
    const float* hb  = (const float*)d_in[5];
    const float* pw  = (const float*)d_in[6];
    const float* pb  = (const float*)d_in[7];
    const float* lnw = (const float*)d_in[8];
    const float* lnb = (const float*)d_in[9];
    float* out = (float*)d_out;

    int Nn = in_sizes[0] / (CCH * HWSZ);

    CM_wconv_kernel<<<(3 * 192 * 192 + 255) / 256, 256>>>(fw, hwm, pw);

    cudaFuncSetAttribute(CM_29540785062535_kernel,
                         cudaFuncAttributeMaxDynamicSharedMemorySize, SMEM_TOTAL);

    int blocks = Nn * (HWSZ / 64);   // 4096
    CM_29540785062535_kernel<<<blocks, NTHR, SMEM_TOTAL>>>(
        x, xl, fw, fb, hb, pb, lnw, lnb, out, Nn);
}